// round 17
// baseline (speedup 1.0000x reference)
#include <cuda_runtime.h>
#include <cuda_fp16.h>
#include <cstdint>

#define N_NODES 10000
#define N_EDGES 320000
#define IN_CH   256
#define OUT_CH  256
#define WPAD    320   // u32 words per bitmap row (need 313, pad to 320)

// Scratch (device globals; no allocation allowed)
__device__ unsigned g_bitmap[N_NODES * WPAD];            // 12.8 MB adjacency bitmap
__device__ int      g_deg[N_NODES];
__device__ __align__(16) __half g_xwh[N_NODES * OUT_CH]; // 5 MB: UNSCALED (X@W) fp16

// ---------------------------------------------------------------------------
// 1) zero bitmap (uint4) + diagonal self-loop bit, deg = 1
// ---------------------------------------------------------------------------
#define INIT_THREADS 256
#define INIT_BLOCKS  3125   // 3125*256 = 800000 = N_NODES*WPAD/4

__global__ void k_init() {
    int i = blockIdx.x * INIT_THREADS + threadIdx.x;   // uint4 index
    int row   = i / 80;            // 80 uint4 per row
    int widx4 = i - row * 80;
    uint4 z = make_uint4(0u, 0u, 0u, 0u);
    int dw = row >> 5;
    if ((dw >> 2) == widx4) {
        unsigned bit = 1u << (row & 31);
        switch (dw & 3) { case 0: z.x = bit; break; case 1: z.y = bit; break;
                          case 2: z.z = bit; break; default: z.w = bit; }
    }
    reinterpret_cast<uint4*>(g_bitmap)[i] = z;
    if (i < N_NODES) g_deg[i] = 1;
}

// ---------------------------------------------------------------------------
// 2) scatter edges; atomicOr return value dedupes degree counting
// ---------------------------------------------------------------------------
__global__ void k_scatter(const int* __restrict__ ei) {
    int e = blockIdx.x * blockDim.x + threadIdx.x;
    if (e >= N_EDGES) return;
    int src = ei[e];
    int dst = ei[N_EDGES + e];
    if ((unsigned)src >= N_NODES || (unsigned)dst >= N_NODES) return; // defensive
    unsigned bit = 1u << (dst & 31);
    unsigned old = atomicOr(&g_bitmap[src * WPAD + (dst >> 5)], bit);
    if (!(old & bit)) atomicAdd(&g_deg[src], 1);
}

// ---------------------------------------------------------------------------
// 3) FP16 tensor-core GEMM (UNSCALED): g_xwh[r][c] = fp16(sum_k x[r][k]*w[k][c])
//    mma.sync.m16n8k16.f32.f16.f16.f32 — K=16 per instruction:
//    8 MMAs + 16 LDS.32 per BK=16 tile (half the tf32 version's issue count).
//    As: fp16 [128 m][16 k], row stride 24 halves (48B) -> lane 4B-bank
//        = (12q+rg) mod 32, all 32 distinct (enumerated).
//    Bs: fp16 TRANSPOSED [64 n][16 k], stride 24 halves -> both B fragment
//        halves are single aligned LDS.32 (consecutive k at fixed n).
//    Fragment map (standard): a0=A[q][2rg,2rg+1], a1=row+8, a2=col+8, a3=both;
//                             b0=B[2rg,2rg+1][q],  b1=k+8.
// ---------------------------------------------------------------------------
#define BM 128
#define BN 64
#define BK 16
#define NTILES (IN_CH / BK)   // 16
#define ASTRH 24              // halves per A row
#define BSTRH 24              // halves per B row (transposed layout)

__device__ __forceinline__ void mma_f16(float* d, const uint32_t* a,
                                        uint32_t b0, uint32_t b1) {
    asm volatile(
        "mma.sync.aligned.m16n8k16.row.col.f32.f16.f16.f32 "
        "{%0,%1,%2,%3}, {%4,%5,%6,%7}, {%8,%9}, {%0,%1,%2,%3};"
        : "+f"(d[0]), "+f"(d[1]), "+f"(d[2]), "+f"(d[3])
        : "r"(a[0]), "r"(a[1]), "r"(a[2]), "r"(a[3]), "r"(b0), "r"(b1));
}

__global__ __launch_bounds__(256) void k_gemm(const float* __restrict__ x,
                                              const float* __restrict__ w) {
    __shared__ __align__(16) __half As[2][BM * ASTRH];   // 2 x 6144 B
    __shared__ __align__(16) __half Bs[2][BN * BSTRH];   // 2 x 3072 B

    int tid  = threadIdx.x;
    int lane = tid & 31;
    int wid  = tid >> 5;
    int wm   = (wid & 3) * 32;   // warp row offset
    int wn   = (wid >> 2) * 32;  // warp col offset
    int q    = lane >> 2;        // 0..7
    int rg   = lane & 3;         // 0..3

    int rowBase = blockIdx.y * BM;
    int colBase = blockIdx.x * BN;

    float acc[2][4][4];
    #pragma unroll
    for (int i = 0; i < 2; i++)
        #pragma unroll
        for (int j = 0; j < 4; j++)
            #pragma unroll
            for (int k = 0; k < 4; k++) acc[i][j][k] = 0.0f;

    float4 aR[2], bR;

    auto loadGlobal = [&](int k0) {
        #pragma unroll
        for (int r = 0; r < 2; r++) {
            int lin  = tid + 256 * r;
            int grow = rowBase + (lin >> 2);
            int cq   = (lin & 3) * 4;
            aR[r] = (grow < N_NODES)
                  ? *reinterpret_cast<const float4*>(&x[grow * IN_CH + k0 + cq])
                  : make_float4(0.f, 0.f, 0.f, 0.f);
        }
        int kk = tid >> 4;             // 0..15
        int cq = (tid & 15) * 4;       // n base 0..60
        bR = *reinterpret_cast<const float4*>(&w[(k0 + kk) * OUT_CH + colBase + cq]);
    };
    auto storeSmem = [&](int buf) {
        #pragma unroll
        for (int r = 0; r < 2; r++) {
            int lin = tid + 256 * r;
            int m   = lin >> 2;
            int cq  = (lin & 3) * 4;   // k offset, multiple of 4
            // addr halves m*24+cq: byte = m*48 + cq*2, both 8B-aligned
            __half2 h01 = __floats2half2_rn(aR[r].x, aR[r].y);
            __half2 h23 = __floats2half2_rn(aR[r].z, aR[r].w);
            uint2 v;
            v.x = *reinterpret_cast<uint32_t*>(&h01);
            v.y = *reinterpret_cast<uint32_t*>(&h23);
            *reinterpret_cast<uint2*>(&As[buf][m * ASTRH + cq]) = v;
        }
        int kk = tid >> 4;
        int cq = (tid & 15) * 4;
        float v[4] = {bR.x, bR.y, bR.z, bR.w};
        #pragma unroll
        for (int j = 0; j < 4; j++)
            Bs[buf][(cq + j) * BSTRH + kk] = __float2half_rn(v[j]);  // transpose
    };

    loadGlobal(0);
    storeSmem(0);
    __syncthreads();

    int cur = 0;
    for (int t = 0; t < NTILES; t++) {
        if (t + 1 < NTILES) loadGlobal((t + 1) * BK);

        // A fragments: 4 LDS.32 per mt
        uint32_t afr[2][4];
        #pragma unroll
        for (int mt = 0; mt < 2; mt++) {
            const __half* base = &As[cur][(wm + mt * 16 + q) * ASTRH + rg * 2];
            afr[mt][0] = *reinterpret_cast<const uint32_t*>(base);
            afr[mt][1] = *reinterpret_cast<const uint32_t*>(base + 8 * ASTRH);
            afr[mt][2] = *reinterpret_cast<const uint32_t*>(base + 8);
            afr[mt][3] = *reinterpret_cast<const uint32_t*>(base + 8 * ASTRH + 8);
        }
        // B fragments: 2 LDS.32 per nt (transposed layout)
        #pragma unroll
        for (int nt = 0; nt < 4; nt++) {
            const __half* base = &Bs[cur][(wn + nt * 8 + q) * BSTRH + rg * 2];
            uint32_t b0 = *reinterpret_cast<const uint32_t*>(base);
            uint32_t b1 = *reinterpret_cast<const uint32_t*>(base + 8);
            #pragma unroll
            for (int mt = 0; mt < 2; mt++)
                mma_f16(acc[mt][nt], afr[mt], b0, b1);
        }

        if (t + 1 < NTILES) {
            int nxt = cur ^ 1;
            storeSmem(nxt);
            __syncthreads();
            cur = nxt;
        }
    }

    // epilogue: pack UNSCALED column pairs into half2 (same acc layout as k8)
    #pragma unroll
    for (int mt = 0; mt < 2; mt++) {
        int r0 = rowBase + wm + mt * 16 + q;
        int r1 = r0 + 8;
        #pragma unroll
        for (int nt = 0; nt < 4; nt++) {
            int c = colBase + wn + nt * 8 + rg * 2;
            if (r0 < N_NODES) {
                __half2 h = __floats2half2_rn(acc[mt][nt][0], acc[mt][nt][1]);
                *reinterpret_cast<__half2*>(&g_xwh[r0 * OUT_CH + c]) = h;
            }
            if (r1 < N_NODES) {
                __half2 h = __floats2half2_rn(acc[mt][nt][2], acc[mt][nt][3]);
                *reinterpret_cast<__half2*>(&g_xwh[r1 * OUT_CH + c]) = h;
            }
        }
    }
}

// ---------------------------------------------------------------------------
// 3b) scale rows by rsqrt(deg) — R11/R16 version (best measured shape).
// ---------------------------------------------------------------------------
__global__ __launch_bounds__(256) void k_scale() {
    int idx = blockIdx.x * 256 + threadIdx.x;   // 1250 * 256 = 320000
    int row = idx >> 5;
    float dv = rsqrtf((float)g_deg[row]);
    uint4 v = reinterpret_cast<uint4*>(g_xwh)[idx];
    __half2* h = reinterpret_cast<__half2*>(&v);
    #pragma unroll
    for (int i = 0; i < 4; i++) {
        float2 f = __half22float2(h[i]);
        h[i] = __floats2half2_rn(f.x * dv, f.y * dv);
    }
    reinterpret_cast<uint4*>(g_xwh)[idx] = v;
}

// ---------------------------------------------------------------------------
// 4) aggregate, warp-per-row over fp16 rows, 4-way HADD2 tree (R13/R16 version).
// ---------------------------------------------------------------------------
#define AGG_WARPS 8
#define MAXDEG    128

__device__ __forceinline__ void add8(float* a, const uint4& v) {
    const __half2* h = reinterpret_cast<const __half2*>(&v);
    #pragma unroll
    for (int i = 0; i < 4; i++) {
        float2 f = __half22float2(h[i]);
        a[2 * i]     += f.x;
        a[2 * i + 1] += f.y;
    }
}

__global__ __launch_bounds__(256) void k_aggregate(float* __restrict__ out) {
    __shared__ int slist[AGG_WARPS][MAXDEG];

    int lane = threadIdx.x & 31;
    int wid  = threadIdx.x >> 5;
    int row  = blockIdx.x * AGG_WARPS + wid;   // grid*8 = 10000 exactly

    const unsigned* rowp = g_bitmap + row * WPAD;

    unsigned wv[10];
    int myc = 0;
    #pragma unroll
    for (int k = 0; k < 10; k++) {
        wv[k] = rowp[lane + 32 * k];
        myc += __popc(wv[k]);
    }

    int inc = myc;
    #pragma unroll
    for (int o = 1; o < 32; o <<= 1) {
        int v = __shfl_up_sync(0xffffffffu, inc, o);
        if (lane >= o) inc += v;
    }
    int deg = __shfl_sync(0xffffffffu, inc, 31);   // true degree (incl. self-loop)
    int off = inc - myc;

    #pragma unroll
    for (int k = 0; k < 10; k++) {
        unsigned w = wv[k];
        int base = (lane + 32 * k) << 5;
        while (w) {
            int b = __ffs(w) - 1;
            w &= w - 1;
            if (off < MAXDEG) slist[wid][off++] = base + b;
        }
    }
    __syncwarp();

    int cnt = deg > MAXDEG ? MAXDEG : deg;

    const uint4* xwh = reinterpret_cast<const uint4*>(g_xwh);  // 32 uint4 per row
    float acc[8] = {0.f, 0.f, 0.f, 0.f, 0.f, 0.f, 0.f, 0.f};

    int n = 0;
    for (; n + 3 < cnt; n += 4) {
        int j0 = slist[wid][n],     j1 = slist[wid][n + 1];
        int j2 = slist[wid][n + 2], j3 = slist[wid][n + 3];
        uint4 va = xwh[j0 * 32 + lane];
        uint4 vb = xwh[j1 * 32 + lane];
        uint4 vc = xwh[j2 * 32 + lane];
        uint4 vd = xwh[j3 * 32 + lane];
        const __half2* ha = reinterpret_cast<const __half2*>(&va);
        const __half2* hb = reinterpret_cast<const __half2*>(&vb);
        const __half2* hc = reinterpret_cast<const __half2*>(&vc);
        const __half2* hd = reinterpret_cast<const __half2*>(&vd);
        #pragma unroll
        for (int i = 0; i < 4; i++) {
            __half2 s01 = __hadd2(ha[i], hb[i]);
            __half2 s23 = __hadd2(hc[i], hd[i]);
            __half2 s   = __hadd2(s01, s23);
            float2 f = __half22float2(s);
            acc[2 * i]     += f.x;
            acc[2 * i + 1] += f.y;
        }
    }
    if (n + 1 < cnt) {
        int j0 = slist[wid][n], j1 = slist[wid][n + 1];
        uint4 va = xwh[j0 * 32 + lane];
        uint4 vb = xwh[j1 * 32 + lane];
        const __half2* ha = reinterpret_cast<const __half2*>(&va);
        const __half2* hb = reinterpret_cast<const __half2*>(&vb);
        #pragma unroll
        for (int i = 0; i < 4; i++) {
            __half2 s = __hadd2(ha[i], hb[i]);
            float2 f = __half22float2(s);
            acc[2 * i]     += f.x;
            acc[2 * i + 1] += f.y;
        }
        n += 2;
    }
    if (n < cnt) {
        uint4 v = xwh[slist[wid][n] * 32 + lane];
        add8(acc, v);
    }

    float dv = rsqrtf((float)deg);
    float4 r0 = make_float4(dv * acc[0], dv * acc[1], dv * acc[2], dv * acc[3]);
    float4 r1 = make_float4(dv * acc[4], dv * acc[5], dv * acc[6], dv * acc[7]);
    float4* out4 = reinterpret_cast<float4*>(out + row * OUT_CH);
    out4[lane * 2]     = r0;
    out4[lane * 2 + 1] = r1;
}

// ---------------------------------------------------------------------------
// Launch: fork-join graph.
//   stream 0 : init -> scatter ----\
//   stream B : gemm (x,w only) -----+--> scale -> aggregate
// ---------------------------------------------------------------------------
extern "C" void kernel_launch(void* const* d_in, const int* in_sizes, int n_in,
                              void* d_out, int out_size) {
    const float* x  = (const float*)d_in[0];   // [10000, 256] f32
    const float* w  = (const float*)d_in[1];   // [256, 256]   f32
    const int*   ei = (const int*)d_in[2];     // [2, 320000]  i32
    float* out = (float*)d_out;                // [10000, 256] f32

    cudaStream_t sB;
    cudaEvent_t evRoot, evGemm;
    cudaStreamCreateWithFlags(&sB, cudaStreamNonBlocking);
    cudaEventCreateWithFlags(&evRoot, cudaEventDisableTiming);
    cudaEventCreateWithFlags(&evGemm, cudaEventDisableTiming);

    cudaEventRecord(evRoot, 0);
    cudaStreamWaitEvent(sB, evRoot, 0);

    dim3 ggrid(OUT_CH / BN, (N_NODES + BM - 1) / BM);   // (4, 79) = 316 blocks
    k_gemm<<<ggrid, 256, 0, sB>>>(x, w);
    cudaEventRecord(evGemm, sB);

    k_init<<<INIT_BLOCKS, INIT_THREADS>>>();
    k_scatter<<<(N_EDGES + 255) / 256, 256>>>(ei);

    cudaStreamWaitEvent(0, evGemm, 0);
    k_scale<<<1250, 256>>>();
    k_aggregate<<<N_NODES / AGG_WARPS, 256>>>(out);
}